// round 13
// baseline (speedup 1.0000x reference)
#include <cuda_runtime.h>
#include <math.h>
#include <stdint.h>

// Problem constants
constexpr int kV = 50257;
constexpr int kH = 512;
constexpr int kS = 512;
constexpr int kB = 8;
constexpr int kT = 64;
constexpr int kM = kT * kB;          // 512 rows (t*B+b)
constexpr int NYB = 393;             // n-tiles of 128 -> 393*128 = 50304
constexpr int kVP = NYB * 128;       // padded row stride (50304)
constexpr int kPAD = kVP - kV;       // 47 pad columns, each contributes exp(0)=1

// Scratch (device globals — allocation-free per harness rules)
__device__ float    g_evp[(size_t)kM * kVP];          // fp32 exp(logit), padded ~103 MB
__device__ uint32_t g_Bp2h[(size_t)NYB * 16 * 2048];  // pre-tiled bf16 W_gen ~51.5 MB
__device__ uint32_t g_At2h[(kH * kM) / 2];            // pre-tiled bf16 A
__device__ float    g_biasp[kVP];                     // zero-padded bias
__device__ float    g_csum[(size_t)kM * kS];
__device__ float    g_psum[(size_t)kM * NYB];         // row-major [m][y]
__device__ float    g_prob[kM];
__device__ float    g_rowsum[kM];
__device__ float    g_zc[kM];
__device__ float    g_q[kS * kB];
__device__ int      g_gid[kB * kS];

// ======================= helpers =======================
__device__ __forceinline__ uint32_t pack_bf16(float lo, float hi) {
    uint32_t r;
    asm("cvt.rn.bf16x2.f32 %0, %1, %2;" : "=r"(r) : "f"(hi), "f"(lo));
    return r;
}
__device__ __forceinline__ uint32_t smem_u32(const void* p) {
    uint32_t a;
    asm("{ .reg .u64 t; cvta.to.shared.u64 t, %1; cvt.u32.u64 %0, t; }" : "=r"(a) : "l"(p));
    return a;
}
#define CP16(dst, src) \
    asm volatile("cp.async.cg.shared.global [%0], [%1], 16;" :: "r"(dst), "l"(src))
#define CPCOMMIT() asm volatile("cp.async.commit_group;" ::: "memory")
#define CPWAIT()   asm volatile("cp.async.wait_group 3;" ::: "memory")

__device__ __forceinline__ void mma_bf16(float* c, const uint4& a, const uint2& b) {
    asm volatile(
        "mma.sync.aligned.m16n8k16.row.col.f32.bf16.bf16.f32 "
        "{%0,%1,%2,%3}, {%4,%5,%6,%7}, {%8,%9}, {%0,%1,%2,%3};"
        : "+f"(c[0]), "+f"(c[1]), "+f"(c[2]), "+f"(c[3])
        : "r"(a.x), "r"(a.y), "r"(a.z), "r"(a.w), "r"(b.x), "r"(b.y));
}

// ======================= fused prep: A-tile + B-tile + leader + q + biaspad =======================
constexpr int PREP_AT = 256;                 // 131072 words, 2/thread
constexpr int PREP_BP = PREP_AT + NYB * 16;  // 6288 bpad blocks
constexpr int PREP_LD = PREP_BP + kB;        // 8 leader blocks
constexpr int PREP_NQ = PREP_LD + 512;       // 4096 q-rows / 8 warps
constexpr int PREP_BI = PREP_NQ + (kVP + 255) / 256;  // 197 bias blocks
__global__ void __launch_bounds__(256) k_prep(const float* __restrict__ A,
                                              const float* __restrict__ Bw,
                                              const float* __restrict__ bias,
                                              const int* __restrict__ src,
                                              const float* __restrict__ mem,
                                              const float* __restrict__ Wp) {
    __shared__ float t[32][129];
    __shared__ int tok[kS];
    int bid = blockIdx.x;
    int tid = threadIdx.x;
    if (bid < PREP_AT) {
#pragma unroll
        for (int i = 0; i < 2; i++) {
            int widx = bid * 512 + tid + i * 256;
            int tile = widx >> 11, within = widx & 2047;
            int mt = tile >> 4, kt = tile & 15;
            int w = within & 3;
            int lane = (within >> 2) & 31;
            int blk = within >> 7;
            int ks2 = blk >> 3, mi = blk & 7;
            int g = lane >> 2, l4 = lane & 3;
            int m = mt * 128 + mi * 16 + (w & 1) * 8 + g;
            int k = kt * 32 + ks2 * 16 + ((w >> 1) & 1) * 8 + l4 * 2;
            const float* ap = A + (size_t)m * kH + k;
            g_At2h[widx] = pack_bf16(ap[0], ap[1]);
        }
    } else if (bid < PREP_BP) {
        int r = bid - PREP_AT;
        int nt = r >> 4, kt = r & 15;
#pragma unroll
        for (int i = 0; i < 16; i++) {
            int idx = tid + i * 256;
            int k = idx >> 7, n = idx & 127;
            int gn = nt * 128 + n;
            t[k][n] = (gn < kV) ? Bw[(size_t)(kt * 32 + k) * kV + gn] : 0.f;
        }
        __syncthreads();
        uint32_t* dst = g_Bp2h + (size_t)(nt * 16 + kt) * 2048;
#pragma unroll
        for (int i = 0; i < 8; i++) {
            int o = tid + i * 256;
            int wsel = o & 1;
            int lane = (o >> 1) & 31;
            int nb = (o >> 6) & 15;
            int ks2 = o >> 10;
            int g = lane >> 2, l4 = lane & 3;
            int k0 = ks2 * 16 + l4 * 2 + wsel * 8;
            int nloc = nb * 8 + g;
            dst[((ks2 * 16 + nb) * 32 + lane) * 2 + wsel] =
                pack_bf16(t[k0][nloc], t[k0 + 1][nloc]);
        }
    } else if (bid < PREP_LD) {
        int b = bid - PREP_BP;
        tok[tid] = src[(size_t)tid * kB + b];
        tok[tid + 256] = src[(size_t)(tid + 256) * kB + b];
        __syncthreads();
        for (int s = tid; s < kS; s += 256) {
            int me = tok[s];
            int gid = s;
            for (int j = 0; j < s; j++)
                if (tok[j] == me) { gid = j; break; }
            g_gid[b * kS + s] = gid;
        }
    } else if (bid < PREP_NQ) {
        int warp = tid >> 5, lane = tid & 31;
        int row = (bid - PREP_LD) * 8 + warp;
        const float4* r4 = (const float4*)(mem + (size_t)row * kH);
        const float4* w4 = (const float4*)Wp;
        float acc = 0.f;
#pragma unroll
        for (int i = 0; i < 4; i++) {
            float4 v = r4[lane + i * 32];
            float4 w = w4[lane + i * 32];
            acc += v.x * w.x + v.y * w.y + v.z * w.z + v.w * w.w;
        }
#pragma unroll
        for (int o = 16; o > 0; o >>= 1) acc += __shfl_down_sync(0xffffffffu, acc, o);
        if (lane == 0) g_q[row] = acc;
    } else {
        int idx = (bid - PREP_NQ) * 256 + tid;
        if (idx < kVP) g_biasp[idx] = (idx < kV) ? bias[idx] : 0.f;
    }
}

// ======================= GEMM: e = exp(A@W + b) fp32 padded (mma.sync bf16) =======================
constexpr int BM = 128, BN = 128;
constexpr int NST = 4;
constexpr int NKT = 16;                     // k-tiles of 32
constexpr int STAGE_WORDS = 4096;           // A 2048 + B 2048 (uint32)
constexpr int GEMM_SMEM = NST * STAGE_WORDS * 4;  // 65536 B

__global__ void __launch_bounds__(256, 1)
k_gemm() {
    extern __shared__ uint32_t sm[];
    const int tid = threadIdx.x;
    const int lane = tid & 31, wid = tid >> 5;
    const int wm = wid & 1, wn = wid >> 1;      // 2 x 4 warp grid
    const int g = lane >> 2, l4 = lane & 3;
    const int mt = blockIdx.x;
    const int by = blockIdx.y;
    const int m0 = mt * BM, n0 = by * BN;
    const uint32_t sbase = smem_u32(sm);

    float acc[4][4][4];
#pragma unroll
    for (int i = 0; i < 4; i++)
#pragma unroll
        for (int j = 0; j < 4; j++)
#pragma unroll
            for (int q = 0; q < 4; q++) acc[i][j][q] = 0.f;

    auto load_tile = [&](int c, int s) {
        uint32_t sa = sbase + s * STAGE_WORDS * 4;
        const uint32_t* asrc = g_At2h + (size_t)(mt * 16 + c) * 2048;
        const uint32_t* bsrc = g_Bp2h + (size_t)(by * 16 + c) * 2048;
#pragma unroll
        for (int i = 0; i < 2; i++) {
            int ch = tid + i * 256;
            CP16(sa + ch * 16, asrc + ch * 4);
            CP16(sa + 8192 + ch * 16, bsrc + ch * 4);
        }
    };

#pragma unroll
    for (int s = 0; s < NST; s++) { load_tile(s, s); CPCOMMIT(); }

#pragma unroll 1
    for (int kt = 0; kt < NKT; kt++) {
        int s = kt % NST;
        CPWAIT();
        __syncthreads();
        const uint4* As = (const uint4*)(sm + s * STAGE_WORDS);
        const uint2* Bs = (const uint2*)(sm + s * STAGE_WORDS + 2048);
#pragma unroll
        for (int ks2 = 0; ks2 < 2; ks2++) {
            uint4 av[4];
            uint2 bv[4];
#pragma unroll
            for (int mf = 0; mf < 4; mf++)
                av[mf] = As[(ks2 * 8 + wm * 4 + mf) * 32 + lane];
#pragma unroll
            for (int nf = 0; nf < 4; nf++)
                bv[nf] = Bs[(ks2 * 16 + wn * 4 + nf) * 32 + lane];
#pragma unroll
            for (int mf = 0; mf < 4; mf++)
#pragma unroll
                for (int nf = 0; nf < 4; nf++)
                    mma_bf16(acc[mf][nf], av[mf], bv[nf]);
        }
        __syncthreads();
        if (kt + NST < NKT) load_tile(kt + NST, s);
        CPCOMMIT();
    }
    __syncthreads();

    // ---------- epilogue: single pass, e = exp(x + bias), unguarded stores ----------
    float* s_s = (float*)sm;           // [128][4]
    float b0[4], b1[4];
#pragma unroll
    for (int nf = 0; nf < 4; nf++) {
        int n = n0 + wn * 32 + nf * 8 + l4 * 2;
        b0[nf] = g_biasp[n];
        b1[nf] = g_biasp[n + 1];
    }
#pragma unroll
    for (int mf = 0; mf < 4; mf++) {
#pragma unroll
        for (int h = 0; h < 2; h++) {
            int rowb = wm * 64 + mf * 16 + g + h * 8;
            float* erow = g_evp + (size_t)(m0 + rowb) * kVP + n0 + wn * 32 + l4 * 2;
            float sum = 0.f;
#pragma unroll
            for (int nf = 0; nf < 4; nf++) {
                float e0 = __expf(acc[mf][nf][h * 2 + 0] + b0[nf]);
                float e1 = __expf(acc[mf][nf][h * 2 + 1] + b1[nf]);
                *(float2*)(erow + nf * 8) = make_float2(e0, e1);
                sum += e0 + e1;
            }
            sum += __shfl_xor_sync(0xffffffffu, sum, 1);
            sum += __shfl_xor_sync(0xffffffffu, sum, 2);
            if (l4 == 0) s_s[rowb * 4 + wn] = sum;
        }
    }
    __syncthreads();
    if (tid < 128) {
        float sum = s_s[tid * 4 + 0] + s_s[tid * 4 + 1] + s_s[tid * 4 + 2] + s_s[tid * 4 + 3];
        if (by == NYB - 1) sum -= (float)kPAD;   // pad cols contribute exp(0)=1 each
        g_psum[(size_t)(m0 + tid) * NYB + by] = sum;
    }
}

// ======================= final row-sum: 1 block per row (parallel, coalesced) =======================
__global__ void __launch_bounds__(128) k_rowfin() {
    int row = blockIdx.x;
    int tid = threadIdx.x;   // 128
    const float* ps = g_psum + (size_t)row * NYB;
    float sum = 0.f;
    for (int y = tid; y < NYB; y += 128) sum += ps[y];
    __shared__ float red[128];
    red[tid] = sum;
    __syncthreads();
    if (tid < 64) red[tid] += red[tid + 64];
    __syncthreads();
    if (tid < 32) {
        float s = red[tid] + red[tid + 32];
#pragma unroll
        for (int o = 16; o > 0; o >>= 1) s += __shfl_xor_sync(0xffffffffu, s, o);
        if (tid == 0) g_rowsum[row] = s;
    }
}

// ======================= Z_c + p_gen per (t,b) =======================
__global__ void k_zc(const float* __restrict__ attn, const float* __restrict__ bp) {
    int m = blockIdx.x;
    int t = m / kB, b = m % kB;
    __shared__ float grp[kS];
    __shared__ float r1[kS], r2[kS], r3[kS];
    int s = threadIdx.x;
    float av = attn[((size_t)b * kT + t) * kS + s];
    int gid = g_gid[b * kS + s];
    grp[s] = 0.f;
    r3[s] = av * g_q[s * kB + b];
    __syncthreads();
    atomicAdd(&grp[gid], av);
    __syncthreads();
    float val = 0.f, cnt = 0.f;
    if (gid == s) {
        float c = grp[s];
        g_csum[(size_t)m * kS + s] = c;
        val = expf(c);
        cnt = 1.f;
    }
    r1[s] = val; r2[s] = cnt;
    __syncthreads();
    for (int off = kS / 2; off > 0; off >>= 1) {
        if (s < off) { r1[s] += r1[s + off]; r2[s] += r2[s + off]; r3[s] += r3[s + off]; }
        __syncthreads();
    }
    if (s == 0) {
        g_zc[m] = ((float)kV - r2[0]) + r1[0];
        float z = r3[0] + bp[0];
        g_prob[m] = 1.f / (1.f + expf(-z));
    }
}

// ======================= dense output: out = log(sgen*e + scopy) (float4) =======================
__global__ void k_logmix(float* __restrict__ out) {
    int m = blockIdx.y;
    const float4* erow = (const float4*)(g_evp + (size_t)m * kVP);  // kVP % 4 == 0
    float* orow = out + (size_t)m * kV;
    float p = g_prob[m];
    float sgen = p / g_rowsum[m];
    float scopy = (1.f - p) / g_zc[m];
    const int nv4 = kVP >> 2;   // 12576
    for (int i = blockIdx.x * 256 + threadIdx.x; i < nv4; i += gridDim.x * 256) {
        float4 e = erow[i];
        int v = i * 4;
        float r0 = __logf(fmaf(sgen, e.x, scopy));
        float r1 = __logf(fmaf(sgen, e.y, scopy));
        float r2 = __logf(fmaf(sgen, e.z, scopy));
        float r3 = __logf(fmaf(sgen, e.w, scopy));
        if (v + 3 < kV) {
            orow[v] = r0; orow[v + 1] = r1; orow[v + 2] = r2; orow[v + 3] = r3;
        } else {
            if (v < kV)     orow[v] = r0;
            if (v + 1 < kV) orow[v + 1] = r1;
            if (v + 2 < kV) orow[v + 2] = r2;
            if (v + 3 < kV) orow[v + 3] = r3;
        }
    }
}

// ======================= sparse copy fixup =======================
__global__ void k_fix(const int* __restrict__ src, float* __restrict__ out) {
    int m = blockIdx.x;
    int b = m % kB;
    int s = threadIdx.x;
    if (g_gid[b * kS + s] != s) return;   // leaders only
    int vv = src[(size_t)s * kB + b];
    float c = g_csum[(size_t)m * kS + s];
    float p = g_prob[m];
    float sgen = p / g_rowsum[m];
    float scopy = (1.f - p) / g_zc[m];
    float e = g_evp[(size_t)m * kVP + vv];
    out[(size_t)m * kV + vv] = __logf(fmaf(sgen, e, scopy * __expf(c)));
}

extern "C" void kernel_launch(void* const* d_in, const int* in_sizes, int n_in,
                              void* d_out, int out_size) {
    const int*   src  = (const int*)d_in[0];    // src_full [S,B] int32
    const float* dec  = (const float*)d_in[1];  // decode_output [T,B,H]
    const float* attn = (const float*)d_in[2];  // decode_attn [B,T,S]
    const float* mem  = (const float*)d_in[3];  // memory [S,B,H]
    const float* Wg   = (const float*)d_in[4];  // W_gen [H,V]
    const float* bg   = (const float*)d_in[5];  // b_gen [V]
    const float* Wp   = (const float*)d_in[6];  // W_prob [H]
    const float* bp   = (const float*)d_in[7];  // b_prob [1]
    float* out = (float*)d_out;                 // [T,B,V] f32

    cudaFuncSetAttribute(k_gemm, cudaFuncAttributeMaxDynamicSharedMemorySize, GEMM_SMEM);

    k_prep<<<PREP_BI, 256>>>(dec, Wg, bg, src, mem, Wp);
    k_zc<<<kM, kS>>>(attn, bp);
    k_gemm<<<dim3(kM / BM, NYB), 256, GEMM_SMEM>>>();
    k_rowfin<<<kM, 128>>>();
    k_logmix<<<dim3(26, kM), 256>>>(out);
    k_fix<<<kM, kS>>>(src, out);
}

// round 14
// speedup vs baseline: 1.4603x; 1.4603x over previous
#include <cuda_runtime.h>
#include <math.h>
#include <stdint.h>

// Problem constants
constexpr int kV = 50257;
constexpr int kH = 512;
constexpr int kS = 512;
constexpr int kB = 8;
constexpr int kT = 64;
constexpr int kM = kT * kB;          // 512 rows (t*B+b)
constexpr int NYB = 393;             // n-tiles of 128 -> 393*128 = 50304
constexpr int kVP = NYB * 128;       // padded row stride (50304)
constexpr int kPAD = kVP - kV;       // 47 pad columns, each contributes exp(0)=1

// Scratch (device globals — allocation-free per harness rules)
__device__ float    g_evp[(size_t)kM * kVP];          // fp32 exp(logit), padded ~103 MB
__device__ uint32_t g_Bp2h[(size_t)NYB * 16 * 2048];  // pre-tiled bf16 W_gen ~51.5 MB
__device__ uint32_t g_At2h[(kH * kM) / 2];            // pre-tiled bf16 A
__device__ float    g_biasp[kVP];                     // zero-padded bias
__device__ float    g_csum[(size_t)kM * kS];
__device__ float    g_psum[(size_t)kM * NYB];         // row-major [m][y]
__device__ float    g_prob[kM];
__device__ float    g_rowsum[kM];
__device__ float    g_zc[kM];
__device__ float    g_q[kS * kB];
__device__ int      g_gid[kB * kS];

// ======================= helpers =======================
__device__ __forceinline__ uint32_t pack_bf16(float lo, float hi) {
    uint32_t r;
    asm("cvt.rn.bf16x2.f32 %0, %1, %2;" : "=r"(r) : "f"(hi), "f"(lo));
    return r;
}
__device__ __forceinline__ uint32_t smem_u32(const void* p) {
    uint32_t a;
    asm("{ .reg .u64 t; cvta.to.shared.u64 t, %1; cvt.u32.u64 %0, t; }" : "=r"(a) : "l"(p));
    return a;
}
#define CP16(dst, src) \
    asm volatile("cp.async.cg.shared.global [%0], [%1], 16;" :: "r"(dst), "l"(src))
#define CPCOMMIT() asm volatile("cp.async.commit_group;" ::: "memory")
#define CPWAIT()   asm volatile("cp.async.wait_group 3;" ::: "memory")

__device__ __forceinline__ void mma_bf16(float* c, const uint4& a, const uint2& b) {
    asm volatile(
        "mma.sync.aligned.m16n8k16.row.col.f32.bf16.bf16.f32 "
        "{%0,%1,%2,%3}, {%4,%5,%6,%7}, {%8,%9}, {%0,%1,%2,%3};"
        : "+f"(c[0]), "+f"(c[1]), "+f"(c[2]), "+f"(c[3])
        : "r"(a.x), "r"(a.y), "r"(a.z), "r"(a.w), "r"(b.x), "r"(b.y));
}

// ======================= fused prep: A-tile + B-tile + leader + q + biaspad =======================
constexpr int PREP_AT = 256;                 // 131072 words, 2/thread
constexpr int PREP_BP = PREP_AT + NYB * 16;  // 6288 bpad blocks
constexpr int PREP_LD = PREP_BP + kB;        // 8 leader blocks
constexpr int PREP_NQ = PREP_LD + 512;       // 4096 q-rows / 8 warps
constexpr int PREP_BI = PREP_NQ + (kVP + 255) / 256;  // 197 bias blocks
__global__ void __launch_bounds__(256) k_prep(const float* __restrict__ A,
                                              const float* __restrict__ Bw,
                                              const float* __restrict__ bias,
                                              const int* __restrict__ src,
                                              const float* __restrict__ mem,
                                              const float* __restrict__ Wp) {
    __shared__ float t[32][129];
    __shared__ int tok[kS];
    int bid = blockIdx.x;
    int tid = threadIdx.x;
    if (bid < PREP_AT) {
#pragma unroll
        for (int i = 0; i < 2; i++) {
            int widx = bid * 512 + tid + i * 256;
            int tile = widx >> 11, within = widx & 2047;
            int mt = tile >> 4, kt = tile & 15;
            int w = within & 3;
            int lane = (within >> 2) & 31;
            int blk = within >> 7;
            int ks2 = blk >> 3, mi = blk & 7;
            int g = lane >> 2, l4 = lane & 3;
            int m = mt * 128 + mi * 16 + (w & 1) * 8 + g;
            int k = kt * 32 + ks2 * 16 + ((w >> 1) & 1) * 8 + l4 * 2;
            const float* ap = A + (size_t)m * kH + k;
            g_At2h[widx] = pack_bf16(ap[0], ap[1]);
        }
    } else if (bid < PREP_BP) {
        int r = bid - PREP_AT;
        int nt = r >> 4, kt = r & 15;
#pragma unroll
        for (int i = 0; i < 16; i++) {
            int idx = tid + i * 256;
            int k = idx >> 7, n = idx & 127;
            int gn = nt * 128 + n;
            t[k][n] = (gn < kV) ? Bw[(size_t)(kt * 32 + k) * kV + gn] : 0.f;
        }
        __syncthreads();
        uint32_t* dst = g_Bp2h + (size_t)(nt * 16 + kt) * 2048;
#pragma unroll
        for (int i = 0; i < 8; i++) {
            int o = tid + i * 256;
            int wsel = o & 1;
            int lane = (o >> 1) & 31;
            int nb = (o >> 6) & 15;
            int ks2 = o >> 10;
            int g = lane >> 2, l4 = lane & 3;
            int k0 = ks2 * 16 + l4 * 2 + wsel * 8;
            int nloc = nb * 8 + g;
            dst[((ks2 * 16 + nb) * 32 + lane) * 2 + wsel] =
                pack_bf16(t[k0][nloc], t[k0 + 1][nloc]);
        }
    } else if (bid < PREP_LD) {
        int b = bid - PREP_BP;
        tok[tid] = src[(size_t)tid * kB + b];
        tok[tid + 256] = src[(size_t)(tid + 256) * kB + b];
        __syncthreads();
        for (int s = tid; s < kS; s += 256) {
            int me = tok[s];
            int gid = s;
            for (int j = 0; j < s; j++)
                if (tok[j] == me) { gid = j; break; }
            g_gid[b * kS + s] = gid;
        }
    } else if (bid < PREP_NQ) {
        int warp = tid >> 5, lane = tid & 31;
        int row = (bid - PREP_LD) * 8 + warp;
        const float4* r4 = (const float4*)(mem + (size_t)row * kH);
        const float4* w4 = (const float4*)Wp;
        float acc = 0.f;
#pragma unroll
        for (int i = 0; i < 4; i++) {
            float4 v = r4[lane + i * 32];
            float4 w = w4[lane + i * 32];
            acc += v.x * w.x + v.y * w.y + v.z * w.z + v.w * w.w;
        }
#pragma unroll
        for (int o = 16; o > 0; o >>= 1) acc += __shfl_down_sync(0xffffffffu, acc, o);
        if (lane == 0) g_q[row] = acc;
    } else {
        int idx = (bid - PREP_NQ) * 256 + tid;
        if (idx < kVP) g_biasp[idx] = (idx < kV) ? bias[idx] : 0.f;
    }
}

// ======================= GEMM: e = exp(A@W + b) fp32 padded (mma.sync bf16) =======================
constexpr int BM = 128, BN = 128;
constexpr int NST = 4;
constexpr int NKT = 16;                     // k-tiles of 32
constexpr int STAGE_WORDS = 4096;           // A 2048 + B 2048 (uint32)
constexpr int GEMM_SMEM = NST * STAGE_WORDS * 4;  // 65536 B

__global__ void __launch_bounds__(256, 1)
k_gemm() {
    extern __shared__ uint32_t sm[];
    const int tid = threadIdx.x;
    const int lane = tid & 31, wid = tid >> 5;
    const int wm = wid & 1, wn = wid >> 1;      // 2 x 4 warp grid
    const int g = lane >> 2, l4 = lane & 3;
    const int mt = blockIdx.x;
    const int by = blockIdx.y;
    const int m0 = mt * BM, n0 = by * BN;
    const uint32_t sbase = smem_u32(sm);

    float acc[4][4][4];
#pragma unroll
    for (int i = 0; i < 4; i++)
#pragma unroll
        for (int j = 0; j < 4; j++)
#pragma unroll
            for (int q = 0; q < 4; q++) acc[i][j][q] = 0.f;

    auto load_tile = [&](int c, int s) {
        uint32_t sa = sbase + s * STAGE_WORDS * 4;
        const uint32_t* asrc = g_At2h + (size_t)(mt * 16 + c) * 2048;
        const uint32_t* bsrc = g_Bp2h + (size_t)(by * 16 + c) * 2048;
#pragma unroll
        for (int i = 0; i < 2; i++) {
            int ch = tid + i * 256;
            CP16(sa + ch * 16, asrc + ch * 4);
            CP16(sa + 8192 + ch * 16, bsrc + ch * 4);
        }
    };

#pragma unroll
    for (int s = 0; s < NST; s++) { load_tile(s, s); CPCOMMIT(); }

#pragma unroll 1
    for (int kt = 0; kt < NKT; kt++) {
        int s = kt % NST;
        CPWAIT();
        __syncthreads();
        const uint4* As = (const uint4*)(sm + s * STAGE_WORDS);
        const uint2* Bs = (const uint2*)(sm + s * STAGE_WORDS + 2048);
#pragma unroll
        for (int ks2 = 0; ks2 < 2; ks2++) {
            uint4 av[4];
            uint2 bv[4];
#pragma unroll
            for (int mf = 0; mf < 4; mf++)
                av[mf] = As[(ks2 * 8 + wm * 4 + mf) * 32 + lane];
#pragma unroll
            for (int nf = 0; nf < 4; nf++)
                bv[nf] = Bs[(ks2 * 16 + wn * 4 + nf) * 32 + lane];
#pragma unroll
            for (int mf = 0; mf < 4; mf++)
#pragma unroll
                for (int nf = 0; nf < 4; nf++)
                    mma_bf16(acc[mf][nf], av[mf], bv[nf]);
        }
        __syncthreads();
        if (kt + NST < NKT) load_tile(kt + NST, s);
        CPCOMMIT();
    }
    __syncthreads();

    // ---------- epilogue: single pass, e = exp(x + bias), unguarded stores ----------
    float* s_s = (float*)sm;           // [128][4]
    float b0[4], b1[4];
#pragma unroll
    for (int nf = 0; nf < 4; nf++) {
        int n = n0 + wn * 32 + nf * 8 + l4 * 2;
        b0[nf] = g_biasp[n];
        b1[nf] = g_biasp[n + 1];
    }
#pragma unroll
    for (int mf = 0; mf < 4; mf++) {
#pragma unroll
        for (int h = 0; h < 2; h++) {
            int rowb = wm * 64 + mf * 16 + g + h * 8;
            float* erow = g_evp + (size_t)(m0 + rowb) * kVP + n0 + wn * 32 + l4 * 2;
            float sum = 0.f;
#pragma unroll
            for (int nf = 0; nf < 4; nf++) {
                float e0 = __expf(acc[mf][nf][h * 2 + 0] + b0[nf]);
                float e1 = __expf(acc[mf][nf][h * 2 + 1] + b1[nf]);
                *(float2*)(erow + nf * 8) = make_float2(e0, e1);
                sum += e0 + e1;
            }
            sum += __shfl_xor_sync(0xffffffffu, sum, 1);
            sum += __shfl_xor_sync(0xffffffffu, sum, 2);
            if (l4 == 0) s_s[rowb * 4 + wn] = sum;
        }
    }
    __syncthreads();
    if (tid < 128) {
        float sum = s_s[tid * 4 + 0] + s_s[tid * 4 + 1] + s_s[tid * 4 + 2] + s_s[tid * 4 + 3];
        if (by == NYB - 1) sum -= (float)kPAD;   // pad cols contribute exp(0)=1 each
        g_psum[(size_t)(m0 + tid) * NYB + by] = sum;
    }
}

// ======================= final row-sum: 1 block per row (parallel, coalesced) =======================
__global__ void __launch_bounds__(128) k_rowfin() {
    int row = blockIdx.x;
    int tid = threadIdx.x;   // 128
    const float* ps = g_psum + (size_t)row * NYB;
    float sum = 0.f;
    for (int y = tid; y < NYB; y += 128) sum += ps[y];
    __shared__ float red[128];
    red[tid] = sum;
    __syncthreads();
    if (tid < 64) red[tid] += red[tid + 64];
    __syncthreads();
    if (tid < 32) {
        float s = red[tid] + red[tid + 32];
#pragma unroll
        for (int o = 16; o > 0; o >>= 1) s += __shfl_xor_sync(0xffffffffu, s, o);
        if (tid == 0) g_rowsum[row] = s;
    }
}

// ======================= Z_c + p_gen per (t,b) =======================
__global__ void k_zc(const float* __restrict__ attn, const float* __restrict__ bp) {
    int m = blockIdx.x;
    int t = m / kB, b = m % kB;
    __shared__ float grp[kS];
    __shared__ float r1[kS], r2[kS], r3[kS];
    int s = threadIdx.x;
    float av = attn[((size_t)b * kT + t) * kS + s];
    int gid = g_gid[b * kS + s];
    grp[s] = 0.f;
    r3[s] = av * g_q[s * kB + b];
    __syncthreads();
    atomicAdd(&grp[gid], av);
    __syncthreads();
    float val = 0.f, cnt = 0.f;
    if (gid == s) {
        float c = grp[s];
        g_csum[(size_t)m * kS + s] = c;
        val = expf(c);
        cnt = 1.f;
    }
    r1[s] = val; r2[s] = cnt;
    __syncthreads();
    for (int off = kS / 2; off > 0; off >>= 1) {
        if (s < off) { r1[s] += r1[s + off]; r2[s] += r2[s + off]; r3[s] += r3[s + off]; }
        __syncthreads();
    }
    if (s == 0) {
        g_zc[m] = ((float)kV - r2[0]) + r1[0];
        float z = r3[0] + bp[0];
        g_prob[m] = 1.f / (1.f + expf(-z));
    }
}

// ======================= dense output: out = log(sgen*e + scopy), streaming stores =======================
__global__ void k_logmix(float* __restrict__ out) {
    int m = blockIdx.y;
    const float4* erow = (const float4*)(g_evp + (size_t)m * kVP);  // kVP % 4 == 0
    float* orow = out + (size_t)m * kV;
    float p = g_prob[m];
    float sgen = p / g_rowsum[m];
    float scopy = (1.f - p) / g_zc[m];
    const int nv4 = kVP >> 2;   // 12576
    for (int i = blockIdx.x * 256 + threadIdx.x; i < nv4; i += gridDim.x * 256) {
        float4 e = erow[i];
        int v = i * 4;
        float r0 = __logf(fmaf(sgen, e.x, scopy));
        float r1 = __logf(fmaf(sgen, e.y, scopy));
        float r2 = __logf(fmaf(sgen, e.z, scopy));
        float r3 = __logf(fmaf(sgen, e.w, scopy));
        // evict-first stores: keep g_evp resident in L2 (103 MB vs 126 MB L2)
        if (v + 3 < kV) {
            __stcs(orow + v, r0);
            __stcs(orow + v + 1, r1);
            __stcs(orow + v + 2, r2);
            __stcs(orow + v + 3, r3);
        } else {
            if (v < kV)     __stcs(orow + v, r0);
            if (v + 1 < kV) __stcs(orow + v + 1, r1);
            if (v + 2 < kV) __stcs(orow + v + 2, r2);
            if (v + 3 < kV) __stcs(orow + v + 3, r3);
        }
    }
}

// ======================= sparse copy fixup =======================
__global__ void k_fix(const int* __restrict__ src, float* __restrict__ out) {
    int m = blockIdx.x;
    int b = m % kB;
    int s = threadIdx.x;
    if (g_gid[b * kS + s] != s) return;   // leaders only
    int vv = src[(size_t)s * kB + b];
    float c = g_csum[(size_t)m * kS + s];
    float p = g_prob[m];
    float sgen = p / g_rowsum[m];
    float scopy = (1.f - p) / g_zc[m];
    float e = g_evp[(size_t)m * kVP + vv];
    __stcs(out + (size_t)m * kV + vv, __logf(fmaf(sgen, e, scopy * __expf(c))));
}

extern "C" void kernel_launch(void* const* d_in, const int* in_sizes, int n_in,
                              void* d_out, int out_size) {
    const int*   src  = (const int*)d_in[0];    // src_full [S,B] int32
    const float* dec  = (const float*)d_in[1];  // decode_output [T,B,H]
    const float* attn = (const float*)d_in[2];  // decode_attn [B,T,S]
    const float* mem  = (const float*)d_in[3];  // memory [S,B,H]
    const float* Wg   = (const float*)d_in[4];  // W_gen [H,V]
    const float* bg   = (const float*)d_in[5];  // b_gen [V]
    const float* Wp   = (const float*)d_in[6];  // W_prob [H]
    const float* bp   = (const float*)d_in[7];  // b_prob [1]
    float* out = (float*)d_out;                 // [T,B,V] f32

    cudaFuncSetAttribute(k_gemm, cudaFuncAttributeMaxDynamicSharedMemorySize, GEMM_SMEM);

    k_prep<<<PREP_BI, 256>>>(dec, Wg, bg, src, mem, Wp);
    k_zc<<<kM, kS>>>(attn, bp);
    k_gemm<<<dim3(kM / BM, NYB), 256, GEMM_SMEM>>>();
    k_rowfin<<<kM, 128>>>();
    k_logmix<<<dim3(26, kM), 256>>>(out);
    k_fix<<<kM, kS>>>(src, out);
}